// round 2
// baseline (speedup 1.0000x reference)
#include <cuda_runtime.h>
#include <cstdint>

#define IN_DIM  8192
#define OUT_DIM 8192
#define BATCH   8192

// Precomputed per-output-column data (written by prep kernel, read by main kernel).
__device__ float4 g_coeff[OUT_DIM];   // (c0, c1, c2, c3) per j
__device__ int2   g_idx[OUT_DIM];     // (idx_a, idx_b) per j

// GATE_COEFFS columns (16 rows x 4 cols, stored column-wise)
__constant__ float GATE0[16] = {0,0,0,0,0,0,0,0, 1, 1, 1, 1, 1, 1, 1, 1};
__constant__ float GATE1[16] = {0,0,1,1,0,0,1,1,-1,-1, 0, 0,-1,-1, 0, 0};
__constant__ float GATE2[16] = {0,0,0,0,1,1,1,1,-1,-1,-1,-1, 0, 0, 0, 0};
__constant__ float GATE3[16] = {0,1,-1,0,-1,0,-2,-1, 1, 2, 0, 1, 0, 1,-1, 0};

// ---------------------------------------------------------------------------
// Prep kernel: softmax(weight[j]/tau) @ GATE -> g_coeff[j]; pack idx -> g_idx.
// Runs once per launch; 8192 threads total, cost is noise.
// ---------------------------------------------------------------------------
__global__ void prep_kernel(const float* __restrict__ weight,
                            const int* __restrict__ idx_a,
                            const int* __restrict__ idx_b) {
    int j = blockIdx.x * blockDim.x + threadIdx.x;
    if (j >= OUT_DIM) return;

    g_idx[j] = make_int2(idx_a[j], idx_b[j]);

    const float4* wrow = reinterpret_cast<const float4*>(weight + (size_t)j * 16);
    float v[16];
    float4 w;
    w = wrow[0]; v[0]=w.x; v[1]=w.y; v[2]=w.z; v[3]=w.w;
    w = wrow[1]; v[4]=w.x; v[5]=w.y; v[6]=w.z; v[7]=w.w;
    w = wrow[2]; v[8]=w.x; v[9]=w.y; v[10]=w.z; v[11]=w.w;
    w = wrow[3]; v[12]=w.x; v[13]=w.y; v[14]=w.z; v[15]=w.w;

    float m = v[0];
    #pragma unroll
    for (int k = 1; k < 16; k++) m = fmaxf(m, v[k]);
    float s = 0.0f;
    #pragma unroll
    for (int k = 0; k < 16; k++) { v[k] = expf(v[k] - m); s += v[k]; }
    float inv = 1.0f / s;

    float c0 = 0.f, c1 = 0.f, c2 = 0.f, c3 = 0.f;
    #pragma unroll
    for (int k = 0; k < 16; k++) {
        float wk = v[k] * inv;
        c0 = fmaf(wk, GATE0[k], c0);
        c1 = fmaf(wk, GATE1[k], c1);
        c2 = fmaf(wk, GATE2[k], c2);
        c3 = fmaf(wk, GATE3[k], c3);
    }
    g_coeff[j] = make_float4(c0, c1, c2, c3);
}

// ---------------------------------------------------------------------------
// cp.async 16B: global -> shared, L1-bypassing (.cg), so streaming row loads
// don't evict the L1-resident idx/coeff metadata (192 KB working set).
// ---------------------------------------------------------------------------
__device__ __forceinline__ void cp_async16(void* smem_dst, const void* gmem_src) {
    uint32_t s = (uint32_t)__cvta_generic_to_shared(smem_dst);
    asm volatile("cp.async.cg.shared.global [%0], [%1], 16;\n" :: "r"(s), "l"(gmem_src));
}

// ---------------------------------------------------------------------------
// Main kernel: one block per batch row. Stage the 32KB row in smem, then
// each thread produces OUT_DIM/256 outputs with random LDS gathers.
// ---------------------------------------------------------------------------
__global__ __launch_bounds__(256) void logic_kernel(const float* __restrict__ x,
                                                    float* __restrict__ out) {
    __shared__ float row[IN_DIM];

    const size_t i = blockIdx.x;
    const float4* src = reinterpret_cast<const float4*>(x + i * (size_t)IN_DIM);
    float4* dst = reinterpret_cast<float4*>(row);

    // 2048 float4 / 256 threads = 8 cp.async per thread (coalesced, L1-bypass)
    #pragma unroll
    for (int t = 0; t < (IN_DIM / 4) / 256; t++) {
        int k = threadIdx.x + t * 256;
        cp_async16(&dst[k], &src[k]);
    }
    asm volatile("cp.async.commit_group;\n");
    asm volatile("cp.async.wait_group 0;\n" ::: "memory");
    __syncthreads();

    float* o = out + i * (size_t)OUT_DIM;

    #pragma unroll 4
    for (int j = threadIdx.x; j < OUT_DIM; j += 256) {
        int2   id = g_idx[j];
        float4 c  = g_coeff[j];
        float a = row[id.x];
        float b = row[id.y];
        // c0 + c1*a + c2*b + c3*(a*b)
        o[j] = fmaf(c.w, a * b, fmaf(c.z, b, fmaf(c.y, a, c.x)));
    }
}

// ---------------------------------------------------------------------------
// Launch: inputs per metadata order: x (f32), weight (f32), idx_a (i32), idx_b (i32)
// ---------------------------------------------------------------------------
extern "C" void kernel_launch(void* const* d_in, const int* in_sizes, int n_in,
                              void* d_out, int out_size) {
    const float* x      = (const float*)d_in[0];
    const float* weight = (const float*)d_in[1];
    const int*   idx_a  = (const int*)d_in[2];
    const int*   idx_b  = (const int*)d_in[3];
    float*       out    = (float*)d_out;

    prep_kernel<<<OUT_DIM / 256, 256>>>(weight, idx_a, idx_b);
    logic_kernel<<<BATCH, 256>>>(x, out);
}

// round 5
// speedup vs baseline: 1.0045x; 1.0045x over previous
#include <cuda_runtime.h>
#include <cuda_fp16.h>
#include <cstdint>

#define IN_DIM  8192
#define OUT_DIM 8192
#define BATCH   8192
#define R       3                       // rows per group (smem-staged)
#define THREADS 512
#define NGROUPS ((BATCH + R - 1) / R)   // 2731 (last group has 2 rows)
#define GRID    152                     // >= SM count; work-stealing makes excess harmless
#define SMEM_BYTES (2 * R * IN_DIM * 4) // double buffer: 192 KB

// One 16B record per output column j:
//   .x = idx_a | (idx_b << 13)   (13 bits each, IN_DIM=8192)
//   .y = c0 (fp32)
//   .z = half2(c1, c2)
//   .w = half2(c3, 0)
__device__ float4   g_meta[OUT_DIM];
__device__ unsigned g_ctr;              // work-stealing counter (reset by prep each launch)

// GATE_COEFFS columns (16 rows x 4 cols, column-wise)
__constant__ float GATE0[16] = {0,0,0,0,0,0,0,0, 1, 1, 1, 1, 1, 1, 1, 1};
__constant__ float GATE1[16] = {0,0,1,1,0,0,1,1,-1,-1, 0, 0,-1,-1, 0, 0};
__constant__ float GATE2[16] = {0,0,0,0,1,1,1,1,-1,-1,-1,-1, 0, 0, 0, 0};
__constant__ float GATE3[16] = {0,1,-1,0,-1,0,-2,-1, 1, 2, 0, 1, 0, 1,-1, 0};

// ---------------------------------------------------------------------------
// Prep: softmax(weight[j]) @ GATE -> packed 16B meta; reset steal counter.
// ---------------------------------------------------------------------------
__global__ void prep_kernel(const float* __restrict__ weight,
                            const int* __restrict__ idx_a,
                            const int* __restrict__ idx_b) {
    int j = blockIdx.x * blockDim.x + threadIdx.x;
    if (j == 0) g_ctr = 0;
    if (j >= OUT_DIM) return;

    const float4* wrow = reinterpret_cast<const float4*>(weight + (size_t)j * 16);
    float v[16];
    #pragma unroll
    for (int q = 0; q < 4; q++) {
        float4 w = wrow[q];
        v[q*4+0] = w.x; v[q*4+1] = w.y; v[q*4+2] = w.z; v[q*4+3] = w.w;
    }
    float m = v[0];
    #pragma unroll
    for (int k = 1; k < 16; k++) m = fmaxf(m, v[k]);
    float s = 0.0f;
    #pragma unroll
    for (int k = 0; k < 16; k++) { v[k] = expf(v[k] - m); s += v[k]; }
    float inv = 1.0f / s;

    float c0 = 0.f, c1 = 0.f, c2 = 0.f, c3 = 0.f;
    #pragma unroll
    for (int k = 0; k < 16; k++) {
        float wk = v[k] * inv;
        c0 = fmaf(wk, GATE0[k], c0);
        c1 = fmaf(wk, GATE1[k], c1);
        c2 = fmaf(wk, GATE2[k], c2);
        c3 = fmaf(wk, GATE3[k], c3);
    }

    unsigned packed = (unsigned)idx_a[j] | ((unsigned)idx_b[j] << 13);
    __half2 c12 = __floats2half2_rn(c1, c2);
    __half2 c3x = __floats2half2_rn(c3, 0.0f);

    float4 rec;
    rec.x = __uint_as_float(packed);
    rec.y = c0;
    rec.z = __uint_as_float(*reinterpret_cast<unsigned*>(&c12));
    rec.w = __uint_as_float(*reinterpret_cast<unsigned*>(&c3x));
    g_meta[j] = rec;
}

// ---------------------------------------------------------------------------
// cp.async.cg 16B (L1-bypassing) global -> shared
// ---------------------------------------------------------------------------
__device__ __forceinline__ void cp_async16(void* smem_dst, const void* gmem_src) {
    uint32_t s = (uint32_t)__cvta_generic_to_shared(smem_dst);
    asm volatile("cp.async.cg.shared.global [%0], [%1], 16;\n" :: "r"(s), "l"(gmem_src));
}
__device__ __forceinline__ void cp_commit() {
    asm volatile("cp.async.commit_group;\n");
}

// Prefetch one group's rows (R rows, tail group may have fewer) into smem buf.
__device__ __forceinline__ void prefetch_group(float* buf, const float* x, int g, int tid) {
    int row0  = g * R;
    int nrows = min(R, BATCH - row0);
    const float4* src = reinterpret_cast<const float4*>(x + (size_t)row0 * IN_DIM);
    float4* dst = reinterpret_cast<float4*>(buf);
    int n4 = nrows * (IN_DIM / 4);
    for (int k = tid; k < n4; k += THREADS) cp_async16(&dst[k], &src[k]);
    cp_commit();
}

// ---------------------------------------------------------------------------
// Main: persistent, double-buffered, work-stealing. One group = R batch rows.
// ---------------------------------------------------------------------------
extern "C" __global__ void __launch_bounds__(THREADS, 1)
logic_kernel(const float* __restrict__ x, float* __restrict__ out) {
    extern __shared__ float sm[];
    __shared__ int s_g;
    const int tid = threadIdx.x;

    // initial steal
    if (tid == 0) s_g = (int)atomicAdd(&g_ctr, 1u);
    __syncthreads();
    int g = s_g;
    if (g >= NGROUPS) return;

    int cur = 0;
    prefetch_group(sm, x, g, tid);

    while (true) {
        // steal next group, start its prefetch into the other buffer
        if (tid == 0) s_g = (int)atomicAdd(&g_ctr, 1u);
        __syncthreads();
        int next = s_g;
        bool has_next = (next < NGROUPS);
        if (has_next) prefetch_group(sm + (cur ^ 1) * (R * IN_DIM), x, next, tid);

        // wait for current group's rows
        if (has_next) asm volatile("cp.async.wait_group 1;\n" ::: "memory");
        else          asm volatile("cp.async.wait_group 0;\n" ::: "memory");
        __syncthreads();

        // compute current group
        const float* buf = sm + cur * (R * IN_DIM);
        int row0  = g * R;
        int nrows = min(R, BATCH - row0);
        float* o0 = out + (size_t)row0 * OUT_DIM;

        if (nrows == R) {
            #pragma unroll 2
            for (int j = tid; j < OUT_DIM; j += THREADS) {
                float4 rec = __ldg(reinterpret_cast<const float4*>(g_meta) + j);
                unsigned packed = __float_as_uint(rec.x);
                unsigned ai = packed & 8191u;
                unsigned bi = packed >> 13;
                float  c0  = rec.y;
                unsigned u12 = __float_as_uint(rec.z);
                unsigned u3  = __float_as_uint(rec.w);
                float2 c12 = __half22float2(*reinterpret_cast<__half2*>(&u12));
                float  c3  = __half2float(*reinterpret_cast<__half*>(&u3));
                #pragma unroll
                for (int r = 0; r < R; r++) {
                    float a = buf[r * IN_DIM + ai];
                    float b = buf[r * IN_DIM + bi];
                    float val = fmaf(c3, a * b, fmaf(c12.y, b, fmaf(c12.x, a, c0)));
                    __stcs(o0 + (size_t)r * OUT_DIM + j, val);
                }
            }
        } else {
            for (int j = tid; j < OUT_DIM; j += THREADS) {
                float4 rec = __ldg(reinterpret_cast<const float4*>(g_meta) + j);
                unsigned packed = __float_as_uint(rec.x);
                unsigned ai = packed & 8191u;
                unsigned bi = packed >> 13;
                float  c0  = rec.y;
                unsigned u12 = __float_as_uint(rec.z);
                unsigned u3  = __float_as_uint(rec.w);
                float2 c12 = __half22float2(*reinterpret_cast<__half2*>(&u12));
                float  c3  = __half2float(*reinterpret_cast<__half*>(&u3));
                for (int r = 0; r < nrows; r++) {
                    float a = buf[r * IN_DIM + ai];
                    float b = buf[r * IN_DIM + bi];
                    float val = fmaf(c3, a * b, fmaf(c12.y, b, fmaf(c12.x, a, c0)));
                    __stcs(o0 + (size_t)r * OUT_DIM + j, val);
                }
            }
        }

        __syncthreads();   // all reads of buf[cur] done before it is refilled
        if (!has_next) break;
        g = next;
        cur ^= 1;
    }
}

// ---------------------------------------------------------------------------
// Launch: x (f32), weight (f32), idx_a (i32), idx_b (i32) -> out (f32)
// ---------------------------------------------------------------------------
extern "C" void kernel_launch(void* const* d_in, const int* in_sizes, int n_in,
                              void* d_out, int out_size) {
    const float* x      = (const float*)d_in[0];
    const float* weight = (const float*)d_in[1];
    const int*   idx_a  = (const int*)d_in[2];
    const int*   idx_b  = (const int*)d_in[3];
    float*       out    = (float*)d_out;

    cudaFuncSetAttribute(logic_kernel,
                         cudaFuncAttributeMaxDynamicSharedMemorySize, SMEM_BYTES);

    prep_kernel<<<OUT_DIM / 256, 256>>>(weight, idx_a, idx_b);
    logic_kernel<<<GRID, THREADS, SMEM_BYTES>>>(x, out);
}

// round 6
// speedup vs baseline: 1.0197x; 1.0152x over previous
#include <cuda_runtime.h>
#include <cuda_fp16.h>
#include <cstdint>

#define IN_DIM  8192
#define OUT_DIM 8192
#define BATCH   8192
#define R       3                       // rows per group (smem-staged)
#define THREADS 1024                    // 32 warps/SM -> occ 50% (was 16 warps / 25%)
#define NGROUPS ((BATCH + R - 1) / R)   // 2731 (last group has 2 rows)
#define GRID    152                     // >= SM count; work-stealing absorbs excess
#define SMEM_BYTES (2 * R * IN_DIM * 4) // double buffer: 192 KB

// One 16B record per output column j:
//   .x = idx_a | (idx_b << 13)   (13 bits each, IN_DIM=8192)
//   .y = c0 (fp32)
//   .z = half2(c1, c2)
//   .w = half2(c3, 0)
__device__ float4   g_meta[OUT_DIM];
__device__ unsigned g_ctr;              // work-stealing counter (reset by prep)

// GATE_COEFFS columns (16 rows x 4 cols, column-wise)
__constant__ float GATE0[16] = {0,0,0,0,0,0,0,0, 1, 1, 1, 1, 1, 1, 1, 1};
__constant__ float GATE1[16] = {0,0,1,1,0,0,1,1,-1,-1, 0, 0,-1,-1, 0, 0};
__constant__ float GATE2[16] = {0,0,0,0,1,1,1,1,-1,-1,-1,-1, 0, 0, 0, 0};
__constant__ float GATE3[16] = {0,1,-1,0,-1,0,-2,-1, 1, 2, 0, 1, 0, 1,-1, 0};

// ---------------------------------------------------------------------------
// Prep: softmax(weight[j]) @ GATE -> packed 16B meta; reset steal counter.
// ---------------------------------------------------------------------------
__global__ void prep_kernel(const float* __restrict__ weight,
                            const int* __restrict__ idx_a,
                            const int* __restrict__ idx_b) {
    int j = blockIdx.x * blockDim.x + threadIdx.x;
    if (j == 0) g_ctr = 0;
    if (j >= OUT_DIM) return;

    const float4* wrow = reinterpret_cast<const float4*>(weight + (size_t)j * 16);
    float v[16];
    #pragma unroll
    for (int q = 0; q < 4; q++) {
        float4 w = wrow[q];
        v[q*4+0] = w.x; v[q*4+1] = w.y; v[q*4+2] = w.z; v[q*4+3] = w.w;
    }
    float m = v[0];
    #pragma unroll
    for (int k = 1; k < 16; k++) m = fmaxf(m, v[k]);
    float s = 0.0f;
    #pragma unroll
    for (int k = 0; k < 16; k++) { v[k] = expf(v[k] - m); s += v[k]; }
    float inv = 1.0f / s;

    float c0 = 0.f, c1 = 0.f, c2 = 0.f, c3 = 0.f;
    #pragma unroll
    for (int k = 0; k < 16; k++) {
        float wk = v[k] * inv;
        c0 = fmaf(wk, GATE0[k], c0);
        c1 = fmaf(wk, GATE1[k], c1);
        c2 = fmaf(wk, GATE2[k], c2);
        c3 = fmaf(wk, GATE3[k], c3);
    }

    unsigned packed = (unsigned)idx_a[j] | ((unsigned)idx_b[j] << 13);
    __half2 c12 = __floats2half2_rn(c1, c2);
    __half2 c3x = __floats2half2_rn(c3, 0.0f);

    float4 rec;
    rec.x = __uint_as_float(packed);
    rec.y = c0;
    rec.z = __uint_as_float(*reinterpret_cast<unsigned*>(&c12));
    rec.w = __uint_as_float(*reinterpret_cast<unsigned*>(&c3x));
    g_meta[j] = rec;
}

// ---------------------------------------------------------------------------
// cp.async.cg 16B (L1-bypassing) global -> shared
// ---------------------------------------------------------------------------
__device__ __forceinline__ void cp_async16(void* smem_dst, const void* gmem_src) {
    uint32_t s = (uint32_t)__cvta_generic_to_shared(smem_dst);
    asm volatile("cp.async.cg.shared.global [%0], [%1], 16;\n" :: "r"(s), "l"(gmem_src));
}
__device__ __forceinline__ void cp_commit() {
    asm volatile("cp.async.commit_group;\n");
}

__device__ __forceinline__ void prefetch_group(float* buf, const float* x, int g, int tid) {
    int row0  = g * R;
    int nrows = min(R, BATCH - row0);
    const float4* src = reinterpret_cast<const float4*>(x + (size_t)row0 * IN_DIM);
    float4* dst = reinterpret_cast<float4*>(buf);
    int n4 = nrows * (IN_DIM / 4);
    for (int k = tid; k < n4; k += THREADS) cp_async16(&dst[k], &src[k]);
    cp_commit();
}

// Per-j work, shared by main/tail paths.
__device__ __forceinline__ void do_j(const float* __restrict__ buf,
                                     float* __restrict__ o0,
                                     int j, int nrows) {
    float4 rec = __ldg(reinterpret_cast<const float4*>(g_meta) + j);
    unsigned packed = __float_as_uint(rec.x);
    unsigned ai = packed & 8191u;
    unsigned bi = packed >> 13;
    float  c0  = rec.y;
    unsigned u12 = __float_as_uint(rec.z);
    unsigned u3  = __float_as_uint(rec.w);
    float2 c12 = __half22float2(*reinterpret_cast<const __half2*>(&u12));
    float  c3  = __half2float(*reinterpret_cast<const __half*>(&u3));

    float a0, a1, a2, b0, b1, b2;
    a0 = buf[0 * IN_DIM + ai]; b0 = buf[0 * IN_DIM + bi];
    if (nrows > 1) { a1 = buf[1 * IN_DIM + ai]; b1 = buf[1 * IN_DIM + bi]; }
    if (nrows > 2) { a2 = buf[2 * IN_DIM + ai]; b2 = buf[2 * IN_DIM + bi]; }

    __stcs(o0 + j, fmaf(c3, a0 * b0, fmaf(c12.y, b0, fmaf(c12.x, a0, c0))));
    if (nrows > 1)
        __stcs(o0 + (size_t)OUT_DIM + j,
               fmaf(c3, a1 * b1, fmaf(c12.y, b1, fmaf(c12.x, a1, c0))));
    if (nrows > 2)
        __stcs(o0 + 2 * (size_t)OUT_DIM + j,
               fmaf(c3, a2 * b2, fmaf(c12.y, b2, fmaf(c12.x, a2, c0))));
}

// ---------------------------------------------------------------------------
// Main: persistent, double-buffered, work-stealing, 1024 threads.
// ---------------------------------------------------------------------------
extern "C" __global__ void __launch_bounds__(THREADS, 1)
logic_kernel(const float* __restrict__ x, float* __restrict__ out) {
    extern __shared__ float sm[];
    __shared__ int s_g;
    const int tid = threadIdx.x;

    if (tid == 0) s_g = (int)atomicAdd(&g_ctr, 1u);
    __syncthreads();
    int g = s_g;
    if (g >= NGROUPS) return;

    int cur = 0;
    prefetch_group(sm, x, g, tid);

    while (true) {
        if (tid == 0) s_g = (int)atomicAdd(&g_ctr, 1u);
        __syncthreads();
        int next = s_g;
        bool has_next = (next < NGROUPS);
        if (has_next) prefetch_group(sm + (cur ^ 1) * (R * IN_DIM), x, next, tid);

        if (has_next) asm volatile("cp.async.wait_group 1;\n" ::: "memory");
        else          asm volatile("cp.async.wait_group 0;\n" ::: "memory");
        __syncthreads();

        const float* buf = sm + cur * (R * IN_DIM);
        int row0  = g * R;
        int nrows = min(R, BATCH - row0);
        float* o0 = out + (size_t)row0 * OUT_DIM;

        if (nrows == R) {
            // 8192 / 1024 = 8 iters; unroll x2 for doubled MLP per warp
            #pragma unroll
            for (int t = 0; t < OUT_DIM / THREADS; t += 2) {
                do_j(buf, o0, tid + t * THREADS, R);
                do_j(buf, o0, tid + (t + 1) * THREADS, R);
            }
        } else {
            for (int j = tid; j < OUT_DIM; j += THREADS)
                do_j(buf, o0, j, nrows);
        }

        __syncthreads();   // all reads of buf[cur] done before refill
        if (!has_next) break;
        g = next;
        cur ^= 1;
    }
}

// ---------------------------------------------------------------------------
// Launch: x (f32), weight (f32), idx_a (i32), idx_b (i32) -> out (f32)
// ---------------------------------------------------------------------------
extern "C" void kernel_launch(void* const* d_in, const int* in_sizes, int n_in,
                              void* d_out, int out_size) {
    const float* x      = (const float*)d_in[0];
    const float* weight = (const float*)d_in[1];
    const int*   idx_a  = (const int*)d_in[2];
    const int*   idx_b  = (const int*)d_in[3];
    float*       out    = (float*)d_out;

    cudaFuncSetAttribute(logic_kernel,
                         cudaFuncAttributeMaxDynamicSharedMemorySize, SMEM_BYTES);

    prep_kernel<<<OUT_DIM / 256, 256>>>(weight, idx_a, idx_b);
    logic_kernel<<<GRID, THREADS, SMEM_BYTES>>>(x, out);
}

// round 8
// speedup vs baseline: 1.2483x; 1.2242x over previous
#include <cuda_runtime.h>
#include <cuda_fp16.h>
#include <cstdint>

#define IN_DIM  8192
#define OUT_DIM 8192
#define BATCH   8192
#define R       2                        // rows per group
#define THREADS 1024
#define NGROUPS (BATCH / R)              // 4096, exact
#define GRID    152
// smem: meta SoA (3 * 32KB) + double-buffered rows (2 * R * 32KB) = 224 KB
#define SMEM_BYTES ((3 * OUT_DIM + 2 * R * IN_DIM) * 4)

// Meta SoA in gmem (filled by prep, copied to smem once per block):
__device__ unsigned g_mIdx[OUT_DIM];   // idx_a | idx_b<<13
__device__ unsigned g_mC01[OUT_DIM];   // half2(c0, c1)
__device__ unsigned g_mC23[OUT_DIM];   // half2(c2, c3)
__device__ unsigned g_ctr;             // work-stealing counter

// GATE_COEFFS columns (16 rows x 4 cols, column-wise)
__constant__ float GATE0[16] = {0,0,0,0,0,0,0,0, 1, 1, 1, 1, 1, 1, 1, 1};
__constant__ float GATE1[16] = {0,0,1,1,0,0,1,1,-1,-1, 0, 0,-1,-1, 0, 0};
__constant__ float GATE2[16] = {0,0,0,0,1,1,1,1,-1,-1,-1,-1, 0, 0, 0, 0};
__constant__ float GATE3[16] = {0,1,-1,0,-1,0,-2,-1, 1, 2, 0, 1, 0, 1,-1, 0};

// ---------------------------------------------------------------------------
// Prep: softmax(weight[j]) @ GATE -> packed SoA meta; reset steal counter.
// ---------------------------------------------------------------------------
__global__ void prep_kernel(const float* __restrict__ weight,
                            const int* __restrict__ idx_a,
                            const int* __restrict__ idx_b) {
    int j = blockIdx.x * blockDim.x + threadIdx.x;
    if (j == 0) g_ctr = 0;
    if (j >= OUT_DIM) return;

    const float4* wrow = reinterpret_cast<const float4*>(weight + (size_t)j * 16);
    float v[16];
    #pragma unroll
    for (int q = 0; q < 4; q++) {
        float4 w = wrow[q];
        v[q*4+0] = w.x; v[q*4+1] = w.y; v[q*4+2] = w.z; v[q*4+3] = w.w;
    }
    float m = v[0];
    #pragma unroll
    for (int k = 1; k < 16; k++) m = fmaxf(m, v[k]);
    float s = 0.0f;
    #pragma unroll
    for (int k = 0; k < 16; k++) { v[k] = expf(v[k] - m); s += v[k]; }
    float inv = 1.0f / s;

    float c0 = 0.f, c1 = 0.f, c2 = 0.f, c3 = 0.f;
    #pragma unroll
    for (int k = 0; k < 16; k++) {
        float wk = v[k] * inv;
        c0 = fmaf(wk, GATE0[k], c0);
        c1 = fmaf(wk, GATE1[k], c1);
        c2 = fmaf(wk, GATE2[k], c2);
        c3 = fmaf(wk, GATE3[k], c3);
    }

    g_mIdx[j] = (unsigned)idx_a[j] | ((unsigned)idx_b[j] << 13);
    __half2 c01 = __floats2half2_rn(c0, c1);
    __half2 c23 = __floats2half2_rn(c2, c3);
    g_mC01[j] = *reinterpret_cast<unsigned*>(&c01);
    g_mC23[j] = *reinterpret_cast<unsigned*>(&c23);
}

// ---------------------------------------------------------------------------
// cp.async.cg 16B global -> shared (streaming, L1-bypassing)
// ---------------------------------------------------------------------------
__device__ __forceinline__ void cp_async16(void* smem_dst, const void* gmem_src) {
    uint32_t s = (uint32_t)__cvta_generic_to_shared(smem_dst);
    asm volatile("cp.async.cg.shared.global [%0], [%1], 16;\n" :: "r"(s), "l"(gmem_src));
}
__device__ __forceinline__ void cp_commit() {
    asm volatile("cp.async.commit_group;\n");
}

// Prefetch one group's R rows into a smem buffer.
__device__ __forceinline__ void prefetch_group(float* buf, const float* x, int g, int tid) {
    const float4* src = reinterpret_cast<const float4*>(x + (size_t)g * R * IN_DIM);
    float4* dst = reinterpret_cast<float4*>(buf);
    #pragma unroll
    for (int t = 0; t < (R * IN_DIM / 4) / THREADS; t++) {
        int k = tid + t * THREADS;
        cp_async16(&dst[k], &src[k]);
    }
    cp_commit();
}

// ---------------------------------------------------------------------------
// Main: persistent, meta resident in smem, double-buffered rows, work-stealing.
// ---------------------------------------------------------------------------
extern "C" __global__ void __launch_bounds__(THREADS, 1)
logic_kernel(const float* __restrict__ x, float* __restrict__ out) {
    extern __shared__ float sm[];
    unsigned* s_idx = reinterpret_cast<unsigned*>(sm);           // [OUT_DIM]
    unsigned* s_c01 = s_idx + OUT_DIM;                           // [OUT_DIM]
    unsigned* s_c23 = s_c01 + OUT_DIM;                           // [OUT_DIM]
    float*    rows  = reinterpret_cast<float*>(s_c23 + OUT_DIM); // [2][R*IN_DIM]
    __shared__ int s_g;

    const int tid = threadIdx.x;

    // Stage metadata once per block (vectorized LDG.128 -> STS.128).
    {
        const uint4* gi = reinterpret_cast<const uint4*>(g_mIdx);
        const uint4* g0 = reinterpret_cast<const uint4*>(g_mC01);
        const uint4* g2 = reinterpret_cast<const uint4*>(g_mC23);
        uint4* si = reinterpret_cast<uint4*>(s_idx);
        uint4* s0 = reinterpret_cast<uint4*>(s_c01);
        uint4* s2 = reinterpret_cast<uint4*>(s_c23);
        #pragma unroll
        for (int t = 0; t < (OUT_DIM / 4) / THREADS + 1; t++) {
            int k = tid + t * THREADS;
            if (k < OUT_DIM / 4) {
                si[k] = gi[k];
                s0[k] = g0[k];
                s2[k] = g2[k];
            }
        }
    }

    if (tid == 0) s_g = (int)atomicAdd(&g_ctr, 1u);
    __syncthreads();                 // covers meta staging + s_g
    int g = s_g;
    if (g >= NGROUPS) return;

    int cur = 0;
    prefetch_group(rows, x, g, tid);

    while (true) {
        if (tid == 0) s_g = (int)atomicAdd(&g_ctr, 1u);
        __syncthreads();
        int next = s_g;
        bool has_next = (next < NGROUPS);
        if (has_next) prefetch_group(rows + (cur ^ 1) * (R * IN_DIM), x, next, tid);

        if (has_next) asm volatile("cp.async.wait_group 1;\n" ::: "memory");
        else          asm volatile("cp.async.wait_group 0;\n" ::: "memory");
        __syncthreads();

        const float* buf = rows + cur * (R * IN_DIM);
        float* o0 = out + (size_t)g * R * OUT_DIM;

        // 8192/1024 = 8 j-iters per thread; pure-smem inner loop.
        #pragma unroll 2
        for (int t = 0; t < OUT_DIM / THREADS; t++) {
            int j = tid + t * THREADS;
            unsigned pk  = s_idx[j];
            unsigned u01 = s_c01[j];
            unsigned u23 = s_c23[j];
            unsigned ai = pk & 8191u;
            unsigned bi = pk >> 13;
            float2 c01 = __half22float2(*reinterpret_cast<const __half2*>(&u01));
            float2 c23 = __half22float2(*reinterpret_cast<const __half2*>(&u23));

            float a0 = buf[ai];
            float b0 = buf[bi];
            float a1 = buf[IN_DIM + ai];
            float b1 = buf[IN_DIM + bi];

            __stcg(o0 + j,
                   fmaf(c23.y, a0 * b0, fmaf(c23.x, b0, fmaf(c01.y, a0, c01.x))));
            __stcg(o0 + OUT_DIM + j,
                   fmaf(c23.y, a1 * b1, fmaf(c23.x, b1, fmaf(c01.y, a1, c01.x))));
        }

        __syncthreads();             // buf[cur] fully consumed before refill
        if (!has_next) break;
        g = next;
        cur ^= 1;
    }
}

// ---------------------------------------------------------------------------
// Launch: x (f32), weight (f32), idx_a (i32), idx_b (i32) -> out (f32)
// ---------------------------------------------------------------------------
extern "C" void kernel_launch(void* const* d_in, const int* in_sizes, int n_in,
                              void* d_out, int out_size) {
    const float* x      = (const float*)d_in[0];
    const float* weight = (const float*)d_in[1];
    const int*   idx_a  = (const int*)d_in[2];
    const int*   idx_b  = (const int*)d_in[3];
    float*       out    = (float*)d_out;

    cudaFuncSetAttribute(logic_kernel,
                         cudaFuncAttributeMaxDynamicSharedMemorySize, SMEM_BYTES);

    prep_kernel<<<OUT_DIM / 256, 256>>>(weight, idx_a, idx_b);
    logic_kernel<<<GRID, THREADS, SMEM_BYTES>>>(x, out);
}